// round 13
// baseline (speedup 1.0000x reference)
#include <cuda_runtime.h>

// Segment-sum out[index[r], :] += src[r, :] (src (nrows,64) fp32 -> out (nseg,64)).
//
// ONE persistent kernel, HARD 32-reg cap (__launch_bounds__(256, 8)) so the
// gather phase keeps 2048 threads/SM (R10's fusion failed at 52 regs/occ 48%):
//   phase 1: grid-stride binning  rank=atomicAdd(cnt[seg]); bucket[seg*64+rank]=r
//   ---- software grid barrier (two-counter, co-residency = grid size) ----
//   phase 2: grid-stride warps over segments; half-warp float4 gather,
//            8 rows (2KB) in flight, predicated 8-wide tail, 256B store.
// Overflow beyond CAP rows/segment goes to an exact side list, consumed in
// phase 2 -> correct for any index distribution (empty for uniform indices).

#define CAP      64
#define MAX_SEG  65536
#define MAX_ROWS 1310720

__device__ int g_ov_cnt;                  // static 0; reset by last block
__device__ unsigned g_c1, g_c2;           // barrier counters; reset by last block
__device__ int g_cnt[MAX_SEG];            // zero at load; reset in phase 2
__device__ int g_bucket[MAX_SEG * CAP];
__device__ int g_ovr[MAX_ROWS];
__device__ int g_ovs[MAX_ROWS];

// Per-warp index-width detection: an int32 array (values in [0,nseg)) read
// as int64 gives huge values with overwhelming probability; the 128B probed
// stays in L1/L2 so recomputing per warp is ~free.
__device__ __forceinline__ bool detect_is64(const void* __restrict__ idx,
                                            int nseg) {
    const long long* p = (const long long*)idx;
    int lane = threadIdx.x & 31;
    long long v = __ldg(p + (lane & 15));
    int ok = (v >= 0 && v < (long long)nseg);
    return __all_sync(0xffffffffu, ok);
}

__device__ __forceinline__ void bin_one(int seg, int row) {
    int rank = atomicAdd(&g_cnt[seg], 1);
    if (rank < CAP) {
        g_bucket[seg * CAP + rank] = row;
    } else {
        int o = atomicAdd(&g_ov_cnt, 1);
        g_ovr[o] = row;
        g_ovs[o] = seg;
    }
}

__global__ __launch_bounds__(256, 8)
void fused_kernel(const float4* __restrict__ src,
                  const void* __restrict__ idx,
                  float4* __restrict__ out,
                  int nrows, int nseg) {
    const bool is64 = detect_is64(idx, nseg);
    const int t    = blockIdx.x * 256 + threadIdx.x;
    const int nthr = gridDim.x * 256;

    // ---------------- phase 1: bin rows by segment (4 rows / iteration)
    const int nquads = nrows >> 2;
    for (int q = t; q < nquads; q += nthr) {
        int base = q * 4;
        int ss[4];
        if (is64) {
            const longlong2* p = (const longlong2*)idx;
            longlong2 a = __ldg(p + (long long)q * 2);
            longlong2 b = __ldg(p + (long long)q * 2 + 1);
            ss[0] = (int)a.x; ss[1] = (int)a.y;
            ss[2] = (int)b.x; ss[3] = (int)b.y;
        } else {
            int4 a = __ldg((const int4*)idx + q);
            ss[0] = a.x; ss[1] = a.y; ss[2] = a.z; ss[3] = a.w;
        }
        #pragma unroll
        for (int k = 0; k < 4; k++) bin_one(ss[k], base + k);
    }
    {   // tail rows (nrows % 4)
        int tail = nrows & 3;
        if (t < tail) {
            int r = nrows - tail + t;
            int seg = is64 ? (int)__ldg((const long long*)idx + r)
                           : __ldg((const int*)idx + r);
            bin_one(seg, r);
        }
    }

    // ---------------- grid barrier (grid size == co-residency limit)
    __syncthreads();
    if (threadIdx.x == 0) {
        __threadfence();
        atomicAdd(&g_c1, 1u);
        while (atomicAdd(&g_c1, 0u) < (unsigned)gridDim.x) __nanosleep(64);
    }
    __syncthreads();
    __threadfence();

    // ---------------- phase 2: grid-stride warps over segments
    const int nwarps = nthr >> 5;
    const int wg     = t >> 5;
    const int lane   = threadIdx.x & 31;
    const int half   = lane >> 4;
    const int c      = lane & 15;

    for (int w = wg; w < nseg; w += nwarps) {
        int n = g_cnt[w];
        int m = (n < CAP) ? n : CAP;
        const int* bkt = g_bucket + w * CAP;

        float4 acc = make_float4(0.f, 0.f, 0.f, 0.f);
        int j = 0;

        int ids[8];
        if (m >= 8) {
            #pragma unroll
            for (int k = 0; k < 8; k++) ids[k] = __ldg(&bkt[k]);
        }
        for (; j + 16 <= m; j += 8) {
            int nid[8];
            #pragma unroll
            for (int k = 0; k < 8; k++) nid[k] = __ldg(&bkt[j + 8 + k]);
            float4 v[4];
            #pragma unroll
            for (int k = 0; k < 4; k++)
                v[k] = __ldcs(src + (long long)ids[half * 4 + k] * 16 + c);
            #pragma unroll
            for (int k = 0; k < 4; k++) {
                acc.x += v[k].x; acc.y += v[k].y;
                acc.z += v[k].z; acc.w += v[k].w;
            }
            #pragma unroll
            for (int k = 0; k < 8; k++) ids[k] = nid[k];
        }
        if (j + 8 <= m) {          // last full batch: ids already in registers
            float4 v[4];
            #pragma unroll
            for (int k = 0; k < 4; k++)
                v[k] = __ldcs(src + (long long)ids[half * 4 + k] * 16 + c);
            #pragma unroll
            for (int k = 0; k < 4; k++) {
                acc.x += v[k].x; acc.y += v[k].y;
                acc.z += v[k].z; acc.w += v[k].w;
            }
            j += 8;
        }
        // Predicated tail: rem = m - j in [0, 8); all loads independent.
        #pragma unroll
        for (int k = 0; k < 4; k++) {
            int rowk = j + half * 4 + k;
            if (rowk < m) {
                int id = __ldg(&bkt[rowk]);
                float4 v = __ldcs(src + (long long)id * 16 + c);
                acc.x += v.x; acc.y += v.y; acc.z += v.z; acc.w += v.w;
            }
        }

        if (n > CAP) {   // exact overflow path (empty for uniform indices)
            int tot = *(volatile int*)&g_ov_cnt;
            for (int o = 0; o < tot; o++) {
                if (__ldg(&g_ovs[o]) == w && half == 0) {
                    int id = __ldg(&g_ovr[o]);
                    float4 v = __ldcs(src + (long long)id * 16 + c);
                    acc.x += v.x; acc.y += v.y; acc.z += v.z; acc.w += v.w;
                }
            }
        }

        // Combine halves: lanes l and l^16 hold partials of the same columns.
        acc.x += __shfl_xor_sync(0xffffffffu, acc.x, 16);
        acc.y += __shfl_xor_sync(0xffffffffu, acc.y, 16);
        acc.z += __shfl_xor_sync(0xffffffffu, acc.z, 16);
        acc.w += __shfl_xor_sync(0xffffffffu, acc.w, 16);

        if (lane == 0) g_cnt[w] = 0;           // clean for the next launch
        if (half == 0)
            out[(long long)w * 16 + c] = acc;  // 16 lanes x 16B = 256B store
    }

    // ---------------- cleanup: last-exiting block resets barrier state.
    // done==gridDim requires EVERY block to have passed the c1 spin and
    // finished phase 2, so no block can still be reading g_c1/g_ov_cnt.
    __syncthreads();
    if (threadIdx.x == 0) {
        __threadfence();
        unsigned done = atomicAdd(&g_c2, 1u) + 1u;
        if (done == (unsigned)gridDim.x) {
            g_ov_cnt = 0;
            atomicExch(&g_c1, 0u);
            atomicExch(&g_c2, 0u);
        }
    }
}

// ----------------------------------------------------------------
extern "C" void kernel_launch(void* const* d_in, const int* in_sizes, int n_in,
                              void* d_out, int out_size) {
    const float4* src = (const float4*)d_in[0];
    const void*   idx = d_in[1];
    float4*       out = (float4*)d_out;

    int nrows = in_sizes[0] / 64;   // 1,250,000
    int nseg  = out_size / 64;      // 50,000

    static int nsm = 0;             // host-side cache; queried once
    if (nsm == 0) {
        cudaDeviceProp prop;
        cudaGetDeviceProperties(&prop, 0);
        nsm = prop.multiProcessorCount;     // 148 (B300) / 152 (GB300)
    }

    // grid == co-residency limit (8 blocks/SM enforced by launch_bounds),
    // so the software grid barrier cannot deadlock.
    fused_kernel<<<nsm * 8, 256>>>(src, idx, out, nrows, nseg);
}

// round 14
// speedup vs baseline: 1.0966x; 1.0966x over previous
#include <cuda_runtime.h>

// Segment-sum out[index[r], :] += src[r, :] (src (nrows,64) fp32 -> out (nseg,64)).
//
// ONE persistent kernel, __launch_bounds__(256, 6) (<=42 regs):
//   R10 fusion failed at 52 regs -> occ 48%; R13 at a hard 32-reg cap -> spills
//   in the hot gather loop. 6 blocks/SM is the spill-free middle: reduce was
//   proven full-speed at ~1680 thr/SM (R6, occ 82%), and 42 regs fits the
//   union of both phases without local-memory traffic.
//   phase 1: grid-stride binning  rank=atomicAdd(cnt[seg]); bucket[seg*64+rank]=r
//   ---- software grid barrier (two-counter; grid == co-residency limit) ----
//   phase 2: grid-stride warps over segments; half-warp float4 gather,
//            8 rows (2KB) in flight, predicated 8-wide tail, 256B store.
// Overflow beyond CAP rows/segment goes to an exact side list, consumed in
// phase 2 -> correct for any index distribution (empty for uniform indices).

#define CAP      64
#define MAX_SEG  65536
#define MAX_ROWS 1310720

__device__ int g_ov_cnt;                  // static 0; reset by last block
__device__ unsigned g_c1, g_c2;           // barrier counters; reset by last block
__device__ int g_cnt[MAX_SEG];            // zero at load; reset in phase 2
__device__ int g_bucket[MAX_SEG * CAP];
__device__ int g_ovr[MAX_ROWS];
__device__ int g_ovs[MAX_ROWS];

// Per-warp index-width detection: an int32 array (values in [0,nseg)) read
// as int64 gives huge values with overwhelming probability; the 128B probed
// stays in L1/L2 so recomputing per warp is ~free.
__device__ __forceinline__ bool detect_is64(const void* __restrict__ idx,
                                            int nseg) {
    const long long* p = (const long long*)idx;
    int lane = threadIdx.x & 31;
    long long v = __ldg(p + (lane & 15));
    int ok = (v >= 0 && v < (long long)nseg);
    return __all_sync(0xffffffffu, ok);
}

__device__ __forceinline__ void bin_one(int seg, int row) {
    int rank = atomicAdd(&g_cnt[seg], 1);
    if (rank < CAP) {
        g_bucket[seg * CAP + rank] = row;
    } else {
        int o = atomicAdd(&g_ov_cnt, 1);
        g_ovr[o] = row;
        g_ovs[o] = seg;
    }
}

__global__ __launch_bounds__(256, 6)
void fused_kernel(const float4* __restrict__ src,
                  const void* __restrict__ idx,
                  float4* __restrict__ out,
                  int nrows, int nseg) {
    const int t    = blockIdx.x * 256 + threadIdx.x;
    const int nthr = gridDim.x * 256;

    // ---------------- phase 1: bin rows by segment (4 rows / iteration)
    // Scoped so its state is dead before the barrier (keeps phase 2 spill-free).
    {
        const bool is64 = detect_is64(idx, nseg);
        const int nquads = nrows >> 2;
        for (int q = t; q < nquads; q += nthr) {
            int base = q * 4;
            int ss[4];
            if (is64) {
                const longlong2* p = (const longlong2*)idx;
                longlong2 a = __ldg(p + (long long)q * 2);
                longlong2 b = __ldg(p + (long long)q * 2 + 1);
                ss[0] = (int)a.x; ss[1] = (int)a.y;
                ss[2] = (int)b.x; ss[3] = (int)b.y;
            } else {
                int4 a = __ldg((const int4*)idx + q);
                ss[0] = a.x; ss[1] = a.y; ss[2] = a.z; ss[3] = a.w;
            }
            #pragma unroll
            for (int k = 0; k < 4; k++) bin_one(ss[k], base + k);
        }
        int tail = nrows & 3;
        if (t < tail) {
            int r = nrows - tail + t;
            int seg = is64 ? (int)__ldg((const long long*)idx + r)
                           : __ldg((const int*)idx + r);
            bin_one(seg, r);
        }
    }

    // ---------------- grid barrier (grid size == co-residency limit)
    __syncthreads();
    if (threadIdx.x == 0) {
        __threadfence();
        atomicAdd(&g_c1, 1u);
        while (atomicAdd(&g_c1, 0u) < (unsigned)gridDim.x) __nanosleep(64);
    }
    __syncthreads();
    __threadfence();

    // ---------------- phase 2: grid-stride warps over segments
    const int nwarps = nthr >> 5;
    const int wg     = t >> 5;
    const int lane   = threadIdx.x & 31;
    const int half   = lane >> 4;
    const int c      = lane & 15;

    for (int w = wg; w < nseg; w += nwarps) {
        int n = g_cnt[w];
        int m = (n < CAP) ? n : CAP;
        const int* bkt = g_bucket + w * CAP;

        float4 acc = make_float4(0.f, 0.f, 0.f, 0.f);
        int j = 0;

        int ids[8];
        if (m >= 8) {
            #pragma unroll
            for (int k = 0; k < 8; k++) ids[k] = __ldg(&bkt[k]);
        }
        for (; j + 16 <= m; j += 8) {
            int nid[8];
            #pragma unroll
            for (int k = 0; k < 8; k++) nid[k] = __ldg(&bkt[j + 8 + k]);
            float4 v[4];
            #pragma unroll
            for (int k = 0; k < 4; k++)
                v[k] = __ldcs(src + (long long)ids[half * 4 + k] * 16 + c);
            #pragma unroll
            for (int k = 0; k < 4; k++) {
                acc.x += v[k].x; acc.y += v[k].y;
                acc.z += v[k].z; acc.w += v[k].w;
            }
            #pragma unroll
            for (int k = 0; k < 8; k++) ids[k] = nid[k];
        }
        if (j + 8 <= m) {          // last full batch: ids already in registers
            float4 v[4];
            #pragma unroll
            for (int k = 0; k < 4; k++)
                v[k] = __ldcs(src + (long long)ids[half * 4 + k] * 16 + c);
            #pragma unroll
            for (int k = 0; k < 4; k++) {
                acc.x += v[k].x; acc.y += v[k].y;
                acc.z += v[k].z; acc.w += v[k].w;
            }
            j += 8;
        }
        // Predicated tail: rem = m - j in [0, 8); all loads independent.
        #pragma unroll
        for (int k = 0; k < 4; k++) {
            int rowk = j + half * 4 + k;
            if (rowk < m) {
                int id = __ldg(&bkt[rowk]);
                float4 v = __ldcs(src + (long long)id * 16 + c);
                acc.x += v.x; acc.y += v.y; acc.z += v.z; acc.w += v.w;
            }
        }

        if (n > CAP) {   // exact overflow path (empty for uniform indices)
            int tot = *(volatile int*)&g_ov_cnt;
            for (int o = 0; o < tot; o++) {
                if (__ldg(&g_ovs[o]) == w && half == 0) {
                    int id = __ldg(&g_ovr[o]);
                    float4 v = __ldcs(src + (long long)id * 16 + c);
                    acc.x += v.x; acc.y += v.y; acc.z += v.z; acc.w += v.w;
                }
            }
        }

        // Combine halves: lanes l and l^16 hold partials of the same columns.
        acc.x += __shfl_xor_sync(0xffffffffu, acc.x, 16);
        acc.y += __shfl_xor_sync(0xffffffffu, acc.y, 16);
        acc.z += __shfl_xor_sync(0xffffffffu, acc.z, 16);
        acc.w += __shfl_xor_sync(0xffffffffu, acc.w, 16);

        if (lane == 0) g_cnt[w] = 0;           // clean for the next launch
        if (half == 0)
            out[(long long)w * 16 + c] = acc;  // 16 lanes x 16B = 256B store
    }

    // ---------------- cleanup: last-exiting block resets barrier state.
    // done==gridDim requires EVERY block to have passed the c1 spin and
    // finished phase 2, so no block can still be reading g_c1/g_ov_cnt.
    __syncthreads();
    if (threadIdx.x == 0) {
        __threadfence();
        unsigned done = atomicAdd(&g_c2, 1u) + 1u;
        if (done == (unsigned)gridDim.x) {
            g_ov_cnt = 0;
            atomicExch(&g_c1, 0u);
            atomicExch(&g_c2, 0u);
        }
    }
}

// ----------------------------------------------------------------
extern "C" void kernel_launch(void* const* d_in, const int* in_sizes, int n_in,
                              void* d_out, int out_size) {
    const float4* src = (const float4*)d_in[0];
    const void*   idx = d_in[1];
    float4*       out = (float4*)d_out;

    int nrows = in_sizes[0] / 64;   // 1,250,000
    int nseg  = out_size / 64;      // 50,000

    static int nsm = 0;             // host-side cache; queried once
    if (nsm == 0) {
        cudaDeviceProp prop;
        cudaGetDeviceProperties(&prop, 0);
        nsm = prop.multiProcessorCount;     // 148 (B300) / 152 (GB300)
    }

    // grid == co-residency limit (6 blocks/SM enforced by launch_bounds),
    // so the software grid barrier cannot deadlock.
    fused_kernel<<<nsm * 6, 256>>>(src, idx, out, nrows, nseg);
}

// round 15
// speedup vs baseline: 1.1501x; 1.0487x over previous
#include <cuda_runtime.h>

// Segment-sum out[index[r], :] += src[r, :] (src (nrows,64) fp32 -> out (nseg,64)).
//
// FINAL FORM: 2-kernel pipeline. Persistent fusion was tried 3x (R10/R13/R14)
// and always collapsed phase-2 DRAM to ~50% (register-union kills the 8-wide
// load batching) regardless of occupancy (48%/73%/98%) -> fusion abandoned.
//   K1 bin:    rank = atomicAdd(cnt[seg]); bucket[seg*64+rank] = r
//              (4 rows/thread, vectorized idx loads, per-warp width detect)
//   K2 reduce: one warp per segment (R6 config: 6250 blocks, regs=32,
//              best measured 57.3us @ DRAM 73%); half-warp float4 gather,
//              8 rows (2KB) in flight with id prefetch, predicated 8-wide
//              tail, one plain 256B store per segment.
// Overflow beyond CAP rows/segment goes to an exact side list (capacity =
// all rows), consumed in reduce -> correct for any index distribution.

#define CAP      64
#define MAX_SEG  65536
#define MAX_ROWS 1310720

__device__ int g_ov_cnt;
__device__ int g_cnt[MAX_SEG];            // zero at load; reset by reduce
__device__ int g_bucket[MAX_SEG * CAP];
__device__ int g_ovr[MAX_ROWS];           // overflow row ids
__device__ int g_ovs[MAX_ROWS];           // overflow seg ids

// Per-warp index-width detection: an int32 array (values in [0,nseg)) read
// as int64 gives huge values with overwhelming probability; the 128B probed
// stays in L1/L2 so recomputing per warp is ~free.
__device__ __forceinline__ bool detect_is64(const void* __restrict__ idx,
                                            int nseg) {
    const long long* p = (const long long*)idx;
    int lane = threadIdx.x & 31;
    long long v = __ldg(p + (lane & 15));
    int ok = (v >= 0 && v < (long long)nseg);
    return __all_sync(0xffffffffu, ok);
}

__device__ __forceinline__ void bin_one(int seg, int row) {
    int rank = atomicAdd(&g_cnt[seg], 1);
    if (rank < CAP) {
        g_bucket[seg * CAP + rank] = row;
    } else {
        int o = atomicAdd(&g_ov_cnt, 1);
        g_ovr[o] = row;
        g_ovs[o] = seg;
    }
}

// ---------------------------------------------------- K1: bin rows by segment
// Thread t owns rows [4t, 4t+4): one int4 (int32 idx) or two longlong2
// (int64 idx) vector loads, then 4 batched atomics+stores.
__global__ __launch_bounds__(256)
void bin_kernel(const void* __restrict__ idx, int nrows, int nseg) {
    bool is64 = detect_is64(idx, nseg);
    if (blockIdx.x == 0 && threadIdx.x == 0) g_ov_cnt = 0;

    int t = blockIdx.x * blockDim.x + threadIdx.x;
    int base = t * 4;

    if (base + 3 < nrows) {
        int ss[4];
        if (is64) {
            const longlong2* p = (const longlong2*)idx;
            longlong2 a = __ldg(p + t * 2);
            longlong2 b = __ldg(p + t * 2 + 1);
            ss[0] = (int)a.x; ss[1] = (int)a.y;
            ss[2] = (int)b.x; ss[3] = (int)b.y;
        } else {
            int4 a = __ldg((const int4*)idx + t);
            ss[0] = a.x; ss[1] = a.y; ss[2] = a.z; ss[3] = a.w;
        }
        #pragma unroll
        for (int k = 0; k < 4; k++) bin_one(ss[k], base + k);
    } else {
        for (int r = base; r < nrows; r++) {
            int seg = is64 ? (int)__ldg((const long long*)idx + r)
                           : __ldg((const int*)idx + r);
            bin_one(seg, r);
        }
    }
}

// ---------------------------------------------------- K2: gather-reduce
// One warp per segment (R6 configuration). Half-warp scheme: lanes 0-15 own
// rows j..j+3 of each 8-row batch, lanes 16-31 own rows j+4..j+7; each lane
// loads float4 (16 lanes x 16B = 256B/row, fully coalesced). 8 rows (2KB)
// in flight per warp; next batch's bucket ids prefetched. Tail handled by
// one predicated 8-wide batch. src read with __ldcs (evict-first).
__global__ __launch_bounds__(256)
void reduce_kernel(const float4* __restrict__ src,
                   float4* __restrict__ out, int nseg) {
    int w    = (blockIdx.x * blockDim.x + threadIdx.x) >> 5;
    int lane = threadIdx.x & 31;
    if (w >= nseg) return;

    int half = lane >> 4;        // 0 or 1
    int c    = lane & 15;        // float4 column within the row

    int n = __ldg(&g_cnt[w]);
    int m = (n < CAP) ? n : CAP;
    const int* bkt = g_bucket + w * CAP;

    float4 acc = make_float4(0.f, 0.f, 0.f, 0.f);
    int j = 0;

    int ids[8];
    if (m >= 8) {
        #pragma unroll
        for (int k = 0; k < 8; k++) ids[k] = __ldg(&bkt[k]);
    }
    for (; j + 16 <= m; j += 8) {
        int nid[8];
        #pragma unroll
        for (int k = 0; k < 8; k++) nid[k] = __ldg(&bkt[j + 8 + k]);
        float4 v[4];
        #pragma unroll
        for (int k = 0; k < 4; k++)
            v[k] = __ldcs(src + (long long)ids[half * 4 + k] * 16 + c);
        #pragma unroll
        for (int k = 0; k < 4; k++) {
            acc.x += v[k].x; acc.y += v[k].y;
            acc.z += v[k].z; acc.w += v[k].w;
        }
        #pragma unroll
        for (int k = 0; k < 8; k++) ids[k] = nid[k];
    }
    if (j + 8 <= m) {            // last full batch: ids already in registers
        float4 v[4];
        #pragma unroll
        for (int k = 0; k < 4; k++)
            v[k] = __ldcs(src + (long long)ids[half * 4 + k] * 16 + c);
        #pragma unroll
        for (int k = 0; k < 4; k++) {
            acc.x += v[k].x; acc.y += v[k].y;
            acc.z += v[k].z; acc.w += v[k].w;
        }
        j += 8;
    }
    // Predicated tail: rem = m - j in [0, 8); all loads independent,
    // issued in one batch (no serial pair round-trips).
    #pragma unroll
    for (int k = 0; k < 4; k++) {
        int rowk = j + half * 4 + k;
        if (rowk < m) {
            int id = __ldg(&bkt[rowk]);
            float4 v = __ldcs(src + (long long)id * 16 + c);
            acc.x += v.x; acc.y += v.y; acc.z += v.z; acc.w += v.w;
        }
    }

    if (n > CAP) {   // exact overflow path (empty for uniform indices)
        int tot = *(volatile int*)&g_ov_cnt;
        for (int o = 0; o < tot; o++) {
            if (__ldg(&g_ovs[o]) == w && half == 0) {
                int id = __ldg(&g_ovr[o]);
                float4 v = __ldcs(src + (long long)id * 16 + c);
                acc.x += v.x; acc.y += v.y; acc.z += v.z; acc.w += v.w;
            }
        }
    }

    // Combine halves: lanes l and l^16 hold partials of the same columns.
    acc.x += __shfl_xor_sync(0xffffffffu, acc.x, 16);
    acc.y += __shfl_xor_sync(0xffffffffu, acc.y, 16);
    acc.z += __shfl_xor_sync(0xffffffffu, acc.z, 16);
    acc.w += __shfl_xor_sync(0xffffffffu, acc.w, 16);

    if (lane == 0) g_cnt[w] = 0;           // leave counts clean for next call
    if (half == 0)
        out[(long long)w * 16 + c] = acc;  // 16 lanes x 16B = 256B store
}

// ----------------------------------------------------------------
extern "C" void kernel_launch(void* const* d_in, const int* in_sizes, int n_in,
                              void* d_out, int out_size) {
    const float4* src = (const float4*)d_in[0];
    const void*   idx = d_in[1];
    float4*       out = (float4*)d_out;

    int nrows = in_sizes[0] / 64;   // 1,250,000
    int nseg  = out_size / 64;      // 50,000

    int bin_threads = (nrows + 3) / 4;
    bin_kernel<<<(bin_threads + 255) / 256, 256>>>(idx, nrows, nseg);

    // One warp per segment (R6 config: 6250 blocks @ 256 threads).
    reduce_kernel<<<(nseg * 32 + 255) / 256, 256>>>(src, out, nseg);
}

// round 16
// speedup vs baseline: 1.1780x; 1.0243x over previous
#include <cuda_runtime.h>

// Segment-sum out[index[r], :] += src[r, :] (src (nrows,64) fp32 -> out (nseg,64)).
//
// 2-kernel pipeline (fusion tried 3x, always collapsed DRAM to ~50% -> dead):
//   K1 bin:    rank = atomicAdd(cnt[seg]); bucket[seg*64+rank] = r
//              + NEW: for rows in the TOP-QUARTER segments (which the reduce
//              processes last), issue ld.global.L2::256B to prefetch the whole
//              256B src row into L2 (~80MB, fits; bin's DRAM pipe is idle).
//              Reduce reads src with __ldcs (evict-first), so its own stream
//              does not evict the prefetched evict-normal lines.
//   K2 reduce: one warp per segment (best measured config: 6250 blocks,
//              57.0us @ DRAM 73.7%); half-warp float4 gather, 8 rows (2KB)
//              in flight with id prefetch, predicated 8-wide tail, one plain
//              256B store per segment.
// Overflow beyond CAP rows/segment goes to an exact side list (capacity =
// all rows), consumed in reduce -> correct for any index distribution.

#define CAP      64
#define MAX_SEG  65536
#define MAX_ROWS 1310720

__device__ int g_ov_cnt;
__device__ int g_cnt[MAX_SEG];            // zero at load; reset by reduce
__device__ int g_bucket[MAX_SEG * CAP];
__device__ int g_ovr[MAX_ROWS];           // overflow row ids
__device__ int g_ovs[MAX_ROWS];           // overflow seg ids

// Per-warp index-width detection: an int32 array (values in [0,nseg)) read
// as int64 gives huge values with overwhelming probability; the 128B probed
// stays in L1/L2 so recomputing per warp is ~free.
__device__ __forceinline__ bool detect_is64(const void* __restrict__ idx,
                                            int nseg) {
    const long long* p = (const long long*)idx;
    int lane = threadIdx.x & 31;
    long long v = __ldg(p + (lane & 15));
    int ok = (v >= 0 && v < (long long)nseg);
    return __all_sync(0xffffffffu, ok);
}

__device__ __forceinline__ void bin_one(int seg, int row) {
    int rank = atomicAdd(&g_cnt[seg], 1);
    if (rank < CAP) {
        g_bucket[seg * CAP + rank] = row;
    } else {
        int o = atomicAdd(&g_ov_cnt, 1);
        g_ovr[o] = row;
        g_ovs[o] = seg;
    }
}

// Prefetch one full 256B src row into L2 (row base is 256B-aligned, so the
// aligned 256B prefetch region == the row). Result is discarded; the load
// itself is 4B. asm volatile keeps it alive.
__device__ __forceinline__ void l2_prefetch_row(const float4* __restrict__ src,
                                                int row) {
    float dummy;
    asm volatile("ld.global.L2::256B.f32 %0, [%1];"
                 : "=f"(dummy)
                 : "l"((const float*)(src + (long long)row * 16))
                 : "memory");
}

// ---------------------------------------------------- K1: bin rows by segment
// Thread t owns rows [4t, 4t+4): one int4 (int32 idx) or two longlong2
// (int64 idx) vector loads, then 4 batched atomics+stores (+L2 prefetch of
// the src row when its segment is in the late-processed top quarter).
__global__ __launch_bounds__(256)
void bin_kernel(const void* __restrict__ idx, const float4* __restrict__ src,
                int nrows, int nseg, int pf_lo) {
    bool is64 = detect_is64(idx, nseg);
    if (blockIdx.x == 0 && threadIdx.x == 0) g_ov_cnt = 0;

    int t = blockIdx.x * blockDim.x + threadIdx.x;
    int base = t * 4;

    if (base + 3 < nrows) {
        int ss[4];
        if (is64) {
            const longlong2* p = (const longlong2*)idx;
            longlong2 a = __ldg(p + t * 2);
            longlong2 b = __ldg(p + t * 2 + 1);
            ss[0] = (int)a.x; ss[1] = (int)a.y;
            ss[2] = (int)b.x; ss[3] = (int)b.y;
        } else {
            int4 a = __ldg((const int4*)idx + t);
            ss[0] = a.x; ss[1] = a.y; ss[2] = a.z; ss[3] = a.w;
        }
        #pragma unroll
        for (int k = 0; k < 4; k++)
            if (ss[k] >= pf_lo) l2_prefetch_row(src, base + k);
        #pragma unroll
        for (int k = 0; k < 4; k++) bin_one(ss[k], base + k);
    } else {
        for (int r = base; r < nrows; r++) {
            int seg = is64 ? (int)__ldg((const long long*)idx + r)
                           : __ldg((const int*)idx + r);
            if (seg >= pf_lo) l2_prefetch_row(src, r);
            bin_one(seg, r);
        }
    }
}

// ---------------------------------------------------- K2: gather-reduce
// One warp per segment. Half-warp scheme: lanes 0-15 own rows j..j+3 of each
// 8-row batch, lanes 16-31 own rows j+4..j+7; each lane loads float4
// (16 lanes x 16B = 256B/row, fully coalesced). 8 rows (2KB) in flight per
// warp; next batch's bucket ids prefetched. Tail handled by one predicated
// 8-wide batch. src read with __ldcs (evict-first: protects the L2-prefetched
// top-quarter rows from being evicted by this stream).
__global__ __launch_bounds__(256)
void reduce_kernel(const float4* __restrict__ src,
                   float4* __restrict__ out, int nseg) {
    int w    = (blockIdx.x * blockDim.x + threadIdx.x) >> 5;
    int lane = threadIdx.x & 31;
    if (w >= nseg) return;

    int half = lane >> 4;        // 0 or 1
    int c    = lane & 15;        // float4 column within the row

    int n = __ldg(&g_cnt[w]);
    int m = (n < CAP) ? n : CAP;
    const int* bkt = g_bucket + w * CAP;

    float4 acc = make_float4(0.f, 0.f, 0.f, 0.f);
    int j = 0;

    int ids[8];
    if (m >= 8) {
        #pragma unroll
        for (int k = 0; k < 8; k++) ids[k] = __ldg(&bkt[k]);
    }
    for (; j + 16 <= m; j += 8) {
        int nid[8];
        #pragma unroll
        for (int k = 0; k < 8; k++) nid[k] = __ldg(&bkt[j + 8 + k]);
        float4 v[4];
        #pragma unroll
        for (int k = 0; k < 4; k++)
            v[k] = __ldcs(src + (long long)ids[half * 4 + k] * 16 + c);
        #pragma unroll
        for (int k = 0; k < 4; k++) {
            acc.x += v[k].x; acc.y += v[k].y;
            acc.z += v[k].z; acc.w += v[k].w;
        }
        #pragma unroll
        for (int k = 0; k < 8; k++) ids[k] = nid[k];
    }
    if (j + 8 <= m) {            // last full batch: ids already in registers
        float4 v[4];
        #pragma unroll
        for (int k = 0; k < 4; k++)
            v[k] = __ldcs(src + (long long)ids[half * 4 + k] * 16 + c);
        #pragma unroll
        for (int k = 0; k < 4; k++) {
            acc.x += v[k].x; acc.y += v[k].y;
            acc.z += v[k].z; acc.w += v[k].w;
        }
        j += 8;
    }
    // Predicated tail: rem = m - j in [0, 8); all loads independent,
    // issued in one batch (no serial pair round-trips).
    #pragma unroll
    for (int k = 0; k < 4; k++) {
        int rowk = j + half * 4 + k;
        if (rowk < m) {
            int id = __ldg(&bkt[rowk]);
            float4 v = __ldcs(src + (long long)id * 16 + c);
            acc.x += v.x; acc.y += v.y; acc.z += v.z; acc.w += v.w;
        }
    }

    if (n > CAP) {   // exact overflow path (empty for uniform indices)
        int tot = *(volatile int*)&g_ov_cnt;
        for (int o = 0; o < tot; o++) {
            if (__ldg(&g_ovs[o]) == w && half == 0) {
                int id = __ldg(&g_ovr[o]);
                float4 v = __ldcs(src + (long long)id * 16 + c);
                acc.x += v.x; acc.y += v.y; acc.z += v.z; acc.w += v.w;
            }
        }
    }

    // Combine halves: lanes l and l^16 hold partials of the same columns.
    acc.x += __shfl_xor_sync(0xffffffffu, acc.x, 16);
    acc.y += __shfl_xor_sync(0xffffffffu, acc.y, 16);
    acc.z += __shfl_xor_sync(0xffffffffu, acc.z, 16);
    acc.w += __shfl_xor_sync(0xffffffffu, acc.w, 16);

    if (lane == 0) g_cnt[w] = 0;           // leave counts clean for next call
    if (half == 0)
        out[(long long)w * 16 + c] = acc;  // 16 lanes x 16B = 256B store
}

// ----------------------------------------------------------------
extern "C" void kernel_launch(void* const* d_in, const int* in_sizes, int n_in,
                              void* d_out, int out_size) {
    const float4* src = (const float4*)d_in[0];
    const void*   idx = d_in[1];
    float4*       out = (float4*)d_out;

    int nrows = in_sizes[0] / 64;   // 1,250,000
    int nseg  = out_size / 64;      // 50,000

    // Prefetch rows whose segment is in the top quarter (~80MB for uniform
    // indices): those segments are processed LAST by the reduce, maximizing
    // L2 survival time of the prefetched lines.
    int pf_lo = nseg - nseg / 4;

    int bin_threads = (nrows + 3) / 4;
    bin_kernel<<<(bin_threads + 255) / 256, 256>>>(idx, src, nrows, nseg, pf_lo);

    // One warp per segment (6250 blocks @ 256 threads).
    reduce_kernel<<<(nseg * 32 + 255) / 256, 256>>>(src, out, nseg);
}